// round 17
// baseline (speedup 1.0000x reference)
#include <cuda_runtime.h>
#include <cuda_fp16.h>
#include <cstdint>
#include <math.h>

#define NHEADS 12
#define NWIN   1152
#define NTOK   64
#define CDIM   384
#define DH     32
#define MROWS  (NWIN * NTOK)   // 73728

typedef unsigned long long ull;

// ---------------------------------------------------------------------------
// Device-global scratch
// ---------------------------------------------------------------------------
__device__ __half g_Qh[MROWS * CDIM];
__device__ __half g_Kh[MROWS * CDIM];
__device__ __half g_Vh[MROWS * CDIM];
__device__ float g_tb[225 * NHEADS];
__device__ float g_ls[NHEADS];
__device__ float g_bcat[3 * CDIM];

__device__ __half g_Ahi[MROWS * CDIM];
__device__ __half g_Alo[MROWS * CDIM];
__device__ __half g_W[CDIM * 1536];

// ---------------------------------------------------------------------------
// helpers
// ---------------------------------------------------------------------------
__device__ __forceinline__ uint32_t smem_u32(const void* p)
{
    uint32_t a;
    asm("{ .reg .u64 t; cvta.to.shared.u64 t, %1; cvt.u32.u64 %0, t; }" : "=r"(a) : "l"(p));
    return a;
}
__device__ __forceinline__ void cp16(uint32_t dst, const void* src)
{
    asm volatile("cp.async.cg.shared.global [%0], [%1], 16;" :: "r"(dst), "l"(src));
}
#define CP_COMMIT() asm volatile("cp.async.commit_group;" ::: "memory")
#define CP_WAIT2()  asm volatile("cp.async.wait_group 2;" ::: "memory")
#define CP_WAIT1()  asm volatile("cp.async.wait_group 1;" ::: "memory")
#define CP_WAIT0()  asm volatile("cp.async.wait_group 0;" ::: "memory")

__device__ __forceinline__ void ldsm_x4(uint32_t r[4], uint32_t addr)
{
    asm volatile("ldmatrix.sync.aligned.m8n8.x4.shared.b16 {%0,%1,%2,%3}, [%4];"
                 : "=r"(r[0]), "=r"(r[1]), "=r"(r[2]), "=r"(r[3]) : "r"(addr));
}
__device__ __forceinline__ void ldsm_x4_t(uint32_t r[4], uint32_t addr)
{
    asm volatile("ldmatrix.sync.aligned.m8n8.x4.trans.shared.b16 {%0,%1,%2,%3}, [%4];"
                 : "=r"(r[0]), "=r"(r[1]), "=r"(r[2]), "=r"(r[3]) : "r"(addr));
}
__device__ __forceinline__ void mma_f16(float c[4], const uint32_t a[4], const uint32_t b[2])
{
    asm volatile(
        "mma.sync.aligned.m16n8k16.row.col.f32.f16.f16.f32 "
        "{%0,%1,%2,%3},{%4,%5,%6,%7},{%8,%9},{%0,%1,%2,%3};"
        : "+f"(c[0]), "+f"(c[1]), "+f"(c[2]), "+f"(c[3])
        : "r"(a[0]), "r"(a[1]), "r"(a[2]), "r"(a[3]), "r"(b[0]), "r"(b[1]));
}

// ---------------------------------------------------------------------------
// Kernel 0a: fp32 -> (fp16 hi, fp16 lo) split
// ---------------------------------------------------------------------------
__global__ void convert_split_kernel(const float* __restrict__ src,
                                     __half* __restrict__ hi,
                                     __half* __restrict__ lo, int n4)
{
    int i = blockIdx.x * blockDim.x + threadIdx.x;
    if (i >= n4) return;
    float4 v = reinterpret_cast<const float4*>(src)[i];
    float vv[4] = {v.x, v.y, v.z, v.w};
    __align__(8) __half h[4], l[4];
    #pragma unroll
    for (int j = 0; j < 4; j++) {
        h[j] = __float2half_rn(vv[j]);
        l[j] = __float2half_rn(vv[j] - __half2float(h[j]));
    }
    reinterpret_cast<uint2*>(hi)[i] = *reinterpret_cast<uint2*>(h);
    reinterpret_cast<uint2*>(lo)[i] = *reinterpret_cast<uint2*>(l);
}

// ---------------------------------------------------------------------------
// Kernel 0b: W[k][n] fp32 -> fp16 plane at column offset
// ---------------------------------------------------------------------------
__global__ void w_fp16_kernel(const float* __restrict__ src,
                              __half* __restrict__ dst,
                              int ncols, int coloff)
{
    int i = blockIdx.x * blockDim.x + threadIdx.x;
    if (i >= 36864) return;
    int k  = i / 96;
    int n4 = (i % 96) * 4;
    float4 v = *reinterpret_cast<const float4*>(&src[(size_t)k * 384 + n4]);
    __align__(8) __half h[4];
    h[0] = __float2half_rn(v.x);
    h[1] = __float2half_rn(v.y);
    h[2] = __float2half_rn(v.z);
    h[3] = __float2half_rn(v.w);
    size_t o = (size_t)k * ncols + coloff + n4;
    *reinterpret_cast<uint2*>(&dst[o]) = *reinterpret_cast<uint2*>(h);
}

__global__ void bias_cat_kernel(const float* __restrict__ bq, const float* __restrict__ bv)
{
    int i = blockIdx.x * blockDim.x + threadIdx.x;
    if (i >= 1152) return;
    g_bcat[i] = (i < 384) ? bq[i] : ((i < 768) ? 0.f : bv[i - 768]);
}

// ---------------------------------------------------------------------------
// Kernel 1: continuous position bias MLP (stores 16*sigmoid directly)
// ---------------------------------------------------------------------------
__global__ void cpb_kernel(const float* __restrict__ w1, const float* __restrict__ b1,
                           const float* __restrict__ w2, const float* __restrict__ b2,
                           const float* __restrict__ tau)
{
    __shared__ float red[128][12];
    const int m   = blockIdx.x;
    const int tid = threadIdx.x;
    const int ai  = m / 15;
    const int bi  = m % 15;

    float x0 = (float)(bi - 7) * (8.0f / 7.0f);
    float x1 = (float)(ai - 7) * (8.0f / 7.0f);
    float s0 = (x0 > 0.f) ? 1.f : ((x0 < 0.f) ? -1.f : 0.f);
    float s1 = (x1 > 0.f) ? 1.f : ((x1 < 0.f) ? -1.f : 0.f);
    float v0 = s0 * log2f(fabsf(x0) + 1.0f) * (1.0f / 3.0f);
    float v1 = s1 * log2f(fabsf(x1) + 1.0f) * (1.0f / 3.0f);

    float p[NHEADS];
    #pragma unroll
    for (int h = 0; h < NHEADS; h++) p[h] = 0.f;

    for (int c = tid; c < 512; c += 128) {
        float hv = v0 * w1[c] + v1 * w1[512 + c] + b1[c];
        hv = fmaxf(hv, 0.0f);
        #pragma unroll
        for (int h = 0; h < NHEADS; h++) p[h] += hv * w2[c * NHEADS + h];
    }
    #pragma unroll
    for (int h = 0; h < NHEADS; h++) red[tid][h] = p[h];
    __syncthreads();

    if (tid < NHEADS) {
        float s = 0.f;
        for (int t2 = 0; t2 < 128; t2++) s += red[t2][tid];
        float v = s + b2[tid];
        g_tb[m * NHEADS + tid] = 16.0f / (1.0f + expf(-v));
        if (m == 0) g_ls[tid] = fmaxf(tau[tid] + 2.302585092994046f, 0.01f);
    }
}

// ---------------------------------------------------------------------------
// Kernel 2: W-resident persistent GEMM.
// W column-slab (384 x 128 cols, padded rows 136 halves) pinned in SMEM once.
// CTA loops over row-blocks (rb = by + it*gridDim.y), streaming A chunks (64 k)
// through a 4-deep cp.async ring. 8 warps (2x4), warp tile 64x32.
// dynamic smem = 384*136*2 + 4*128*72*2 = 104448 + 73728 = 178176 B
// ---------------------------------------------------------------------------
#define WSLAB_BYTES 104448
#define ACH_BYTES   18432
#define GEMM_SMEM   (WSLAB_BYTES + 4 * ACH_BYTES)

__global__ __launch_bounds__(256, 1) void gemm_wres_kernel(
    const __half* __restrict__ Ahi, const __half* __restrict__ Alo,
    const __half* __restrict__ W,
    const float* __restrict__ bias,
    void* C0, void* C1, void* C2, int Ntot, int half_out, int nrb)
{
    extern __shared__ __align__(128) char smem[];
    __shared__ float bias_s[128];
    const uint32_t wsb = smem_u32(smem);                 // W slab
    const uint32_t arb = wsb + WSLAB_BYTES;              // A ring base
    const int tid  = threadIdx.x;
    const int lane = tid & 31;
    const int warp = tid >> 5;
    const int wm   = warp >> 2;        // 0..1
    const int wn   = warp & 3;         // 0..3
    const int cb   = blockIdx.x * 128;
    const int gid  = cb / 384;
    void* C = (gid == 0) ? C0 : ((gid == 1) ? C1 : C2);

    const int g  = lane >> 3;
    const int lr = lane & 7;
    const int a_row  = wm * 64 + lr + (g & 1) * 8;
    const int a_col  = (g >> 1) * 8;
    const int b_krow = lr + (g & 1) * 8;
    const int b_ncol = wn * 32 + (g >> 1) * 8;

    // bias staging
    if (tid < 128) bias_s[tid] = bias[cb + tid];

    // load W slab: 384 rows x 128 halves (16 x 16B segs per row)
    #pragma unroll 4
    for (int i = 0; i < 24; i++) {
        int id = tid + i * 256;          // 0..6143
        int r  = id >> 4;                // 0..383
        int cc = id & 15;
        cp16(wsb + r * 272 + cc * 16, &W[(size_t)r * Ntot + cb + cc * 8]);
    }
    CP_COMMIT();

    // A chunk stager
    auto stageA = [&](int rb, int c) {
        const int kl = (c % 6) * 64;
        const __half* pA = (c < 6) ? Ahi : Alo;
        const uint32_t st = arb + (c & 3) * ACH_BYTES;
        #pragma unroll
        for (int i = 0; i < 4; i++) {
            int id = tid + i * 256;      // 0..1023
            int r  = id >> 3;            // 0..127
            int cc = id & 7;
            cp16(st + r * 144 + cc * 16,
                 &pA[(size_t)(rb + r) * 384 + kl + cc * 8]);
        }
    };

    for (int it = 0; it < nrb; it++) {
        const int rb = (blockIdx.y + it * gridDim.y) * 128;

        float acc[4][4][4];
        #pragma unroll
        for (int mi = 0; mi < 4; mi++)
            #pragma unroll
            for (int ni = 0; ni < 4; ni++)
                #pragma unroll
                for (int q = 0; q < 4; q++) acc[mi][ni][q] = 0.f;

        stageA(rb, 0); CP_COMMIT();
        stageA(rb, 1); CP_COMMIT();
        stageA(rb, 2); CP_COMMIT();

        for (int c = 0; c < 12; c++) {
            if (c < 10) CP_WAIT2();
            else if (c == 10) CP_WAIT1();
            else CP_WAIT0();
            __syncthreads();
            if (c + 3 < 12) { stageA(rb, c + 3); CP_COMMIT(); }

            const uint32_t sA = arb + (c & 3) * ACH_BYTES;
            const int kl = (c % 6) * 64;
            #pragma unroll
            for (int ks = 0; ks < 4; ks++) {
                uint32_t af[4][4];
                #pragma unroll
                for (int mi = 0; mi < 4; mi++)
                    ldsm_x4(af[mi], sA + ((a_row + mi * 16) * 72 + ks * 16 + a_col) * 2);
                uint32_t bf_[2][4];
                #pragma unroll
                for (int nt = 0; nt < 2; nt++)
                    ldsm_x4_t(bf_[nt], wsb + ((kl + ks * 16 + b_krow) * 136 + b_ncol + nt * 16) * 2);
                #pragma unroll
                for (int mi = 0; mi < 4; mi++)
                    #pragma unroll
                    for (int ni = 0; ni < 4; ni++)
                        mma_f16(acc[mi][ni], af[mi], &bf_[ni >> 1][(ni & 1) * 2]);
            }
        }

        // epilogue for this row-block
        #pragma unroll
        for (int mi = 0; mi < 4; mi++) {
            #pragma unroll
            for (int ni = 0; ni < 4; ni++) {
                int r    = rb + wm * 64 + mi * 16 + (lane >> 2);
                int cl   = wn * 32 + ni * 8 + (lane & 3) * 2;
                int cc   = cb + cl - gid * 384;
                float b0 = bias_s[cl];
                float b1 = bias_s[cl + 1];
                float o00 = acc[mi][ni][0] + b0, o01 = acc[mi][ni][1] + b1;
                float o10 = acc[mi][ni][2] + b0, o11 = acc[mi][ni][3] + b1;
                if (half_out) {
                    __half* Ch = (__half*)C;
                    *reinterpret_cast<__half2*>(&Ch[(size_t)r * 384 + cc])       = __floats2half2_rn(o00, o01);
                    *reinterpret_cast<__half2*>(&Ch[(size_t)(r + 8) * 384 + cc]) = __floats2half2_rn(o10, o11);
                } else {
                    float* Cf = (float*)C;
                    *reinterpret_cast<float2*>(&Cf[(size_t)r * 384 + cc])       = make_float2(o00, o01);
                    *reinterpret_cast<float2*>(&Cf[(size_t)(r + 8) * 384 + cc]) = make_float2(o10, o11);
                }
            }
        }
    }
}

// ---------------------------------------------------------------------------
// Kernel 3: tensor-core attention (unchanged from round 16)
// ---------------------------------------------------------------------------
__global__ __launch_bounds__(128) void attn_tc_kernel(const float* __restrict__ mask)
{
    __shared__ __align__(16) __half qsm[64 * 40];
    __shared__ __align__(16) __half ksm[64 * 40];
    __shared__ __align__(16) __half vsm[64 * 40];
    __shared__ float msk[64 * 65];
    __shared__ float tbs[225];
    __shared__ float qn[64];
    __shared__ float kn[64];

    const int b = blockIdx.x, h = blockIdx.y, tid = threadIdx.x;
    const int warp = tid >> 5, lane = tid & 31;

    const size_t base = (size_t)b * NTOK * CDIM + h * DH;
    for (int idx = tid; idx < 256; idx += 128) {
        int n = idx >> 2, ch = (idx & 3) * 8;
        size_t ga = base + (size_t)n * CDIM + ch;
        *reinterpret_cast<uint4*>(&qsm[n * 40 + ch]) = *reinterpret_cast<const uint4*>(&g_Qh[ga]);
        *reinterpret_cast<uint4*>(&ksm[n * 40 + ch]) = *reinterpret_cast<const uint4*>(&g_Kh[ga]);
        *reinterpret_cast<uint4*>(&vsm[n * 40 + ch]) = *reinterpret_cast<const uint4*>(&g_Vh[ga]);
    }
    for (int i = tid; i < 225; i += 128) tbs[i] = g_tb[i * NHEADS + h];
    {
        const float4* mp = reinterpret_cast<const float4*>(mask + (size_t)b * 4096);
        for (int idx = tid; idx < 1024; idx += 128) {
            float4 mv = mp[idx];
            int f = idx << 2;
            int i = f >> 6, j = f & 63;
            msk[i * 65 + j]     = mv.x;
            msk[i * 65 + j + 1] = mv.y;
            msk[i * 65 + j + 2] = mv.z;
            msk[i * 65 + j + 3] = mv.w;
        }
    }
    const float ls = g_ls[h];
    __syncthreads();

    {
        int t = (tid < 64) ? tid : (tid - 64);
        const __half2* p = reinterpret_cast<const __half2*>((tid < 64) ? &qsm[t * 40] : &ksm[t * 40]);
        float s = 0.f;
        #pragma unroll
        for (int u = 0; u < 16; u++) {
            float2 f = __half22float2(p[u]);
            s += f.x * f.x + f.y * f.y;
        }
        if (tid < 64) qn[t] = sqrtf(s); else kn[t] = sqrtf(s);
    }
    __syncthreads();

    const int rw = warp * 16;
    const int g  = lane >> 3, lr = lane & 7;
    const uint32_t qsb = smem_u32(qsm), ksb = smem_u32(ksm), vsb = smem_u32(vsm);

    uint32_t aq[2][4];
    #pragma unroll
    for (int ks = 0; ks < 2; ks++)
        ldsm_x4(aq[ks], qsb + (uint32_t)(((rw + lr + (g & 1) * 8) * 40 + ks * 16 + (g >> 1) * 8) * 2));

    float c[8][4];
    #pragma unroll
    for (int nt = 0; nt < 8; nt++)
        #pragma unroll
        for (int q = 0; q < 4; q++) c[nt][q] = 0.f;

    #pragma unroll
    for (int jt = 0; jt < 4; jt++) {
        #pragma unroll
        for (int ks = 0; ks < 2; ks++) {
            uint32_t kb[4];
            ldsm_x4(kb, ksb + (uint32_t)(((jt * 16 + lr + (g >> 1) * 8) * 40 + ks * 16 + (g & 1) * 8) * 2));
            mma_f16(c[jt * 2],     aq[ks], &kb[0]);
            mma_f16(c[jt * 2 + 1], aq[ks], &kb[2]);
        }
    }

    const int r   = lane >> 2;
    const int cc2 = (lane & 3) * 2;
    const int i0 = rw + r, i1 = i0 + 8;
    const float qn0 = qn[i0], qn1 = qn[i1];
    const int ri0 = i0 >> 3, ci0 = i0 & 7;
    const int ri1 = i1 >> 3, ci1 = i1 & 7;

    #pragma unroll
    for (int nt = 0; nt < 8; nt++) {
        #pragma unroll
        for (int q = 0; q < 2; q++) {
            int j = nt * 8 + cc2 + q;
            float knj = kn[j];
            int rj = j >> 3, cj = j & 7;
            float b0 = tbs[((ri0 - rj) + 7) * 15 + (ci0 - cj) + 7] + msk[i0 * 65 + j];
            float b1 = tbs[((ri1 - rj) + 7) * 15 + (ci1 - cj) + 7] + msk[i1 * 65 + j];
            c[nt][q]     = c[nt][q]     * __fdividef(ls, fmaxf(qn0 * knj, 1e-6f)) + b0;
            c[nt][q + 2] = c[nt][q + 2] * __fdividef(ls, fmaxf(qn1 * knj, 1e-6f)) + b1;
        }
    }

    {
        float mx0 = -1e30f, mx1 = -1e30f;
        #pragma unroll
        for (int nt = 0; nt < 8; nt++) {
            mx0 = fmaxf(mx0, fmaxf(c[nt][0], c[nt][1]));
            mx1 = fmaxf(mx1, fmaxf(c[nt][2], c[nt][3]));
        }
        mx0 = fmaxf(mx0, __shfl_xor_sync(0xffffffffu, mx0, 1));
        mx0 = fmaxf(mx0, __shfl_xor_sync(0xffffffffu, mx0, 2));
        mx1 = fmaxf(mx1, __shfl_xor_sync(0xffffffffu, mx1, 1));
        mx1 = fmaxf(mx1, __shfl_xor_sync(0xffffffffu, mx1, 2));
        float s0 = 0.f, s1 = 0.f;
        #pragma unroll
        for (int nt = 0; nt < 8; nt++) {
            c[nt][0] = __expf(c[nt][0] - mx0); s0 += c[nt][0];
            c[nt][1] = __expf(c[nt][1] - mx0); s0 += c[nt][1];
            c[nt][2] = __expf(c[nt][2] - mx1); s1 += c[nt][2];
            c[nt][3] = __expf(c[nt][3] - mx1); s1 += c[nt][3];
        }
        s0 += __shfl_xor_sync(0xffffffffu, s0, 1);
        s0 += __shfl_xor_sync(0xffffffffu, s0, 2);
        s1 += __shfl_xor_sync(0xffffffffu, s1, 1);
        s1 += __shfl_xor_sync(0xffffffffu, s1, 2);
        float inv0 = 1.0f / s0, inv1 = 1.0f / s1;
        #pragma unroll
        for (int nt = 0; nt < 8; nt++) {
            c[nt][0] *= inv0; c[nt][1] *= inv0;
            c[nt][2] *= inv1; c[nt][3] *= inv1;
        }
    }

    uint32_t ap[4][4], apl[4][4];
    #pragma unroll
    for (int kt = 0; kt < 4; kt++) {
        #pragma unroll
        for (int half_idx = 0; half_idx < 4; half_idx++) {
            int nt = kt * 2 + (half_idx >> 1);
            int q0 = (half_idx & 1) * 2;
            float v0 = c[nt][q0], v1 = c[nt][q0 + 1];
            __half h0 = __float2half_rn(v0);
            __half h1 = __float2half_rn(v1);
            __half l0 = __float2half_rn(v0 - __half2float(h0));
            __half l1 = __float2half_rn(v1 - __half2float(h1));
            __half2 hh = __halves2half2(h0, h1);
            __half2 lh = __halves2half2(l0, l1);
            ap[kt][half_idx]  = *reinterpret_cast<uint32_t*>(&hh);
            apl[kt][half_idx] = *reinterpret_cast<uint32_t*>(&lh);
        }
    }

    float dacc[4][4];
    #pragma unroll
    for (int nt = 0; nt < 4; nt++)
        #pragma unroll
        for (int q = 0; q < 4; q++) dacc[nt][q] = 0.f;

    #pragma unroll
    for (int kt = 0; kt < 4; kt++) {
        #pragma unroll
        for (int vt = 0; vt < 2; vt++) {
            uint32_t vb[4];
            ldsm_x4_t(vb, vsb + (uint32_t)(((kt * 16 + lr + (g & 1) * 8) * 40 + vt * 16 + (g >> 1) * 8) * 2));
            mma_f16(dacc[vt * 2],     ap[kt],  &vb[0]);
            mma_f16(dacc[vt * 2 + 1], ap[kt],  &vb[2]);
            mma_f16(dacc[vt * 2],     apl[kt], &vb[0]);
            mma_f16(dacc[vt * 2 + 1], apl[kt], &vb[2]);
        }
    }

    #pragma unroll
    for (int nt = 0; nt < 4; nt++) {
        int col = h * DH + nt * 8 + cc2;
        #pragma unroll
        for (int rr = 0; rr < 2; rr++) {
            int ii = rr ? i1 : i0;
            float v0 = dacc[nt][rr * 2], v1 = dacc[nt][rr * 2 + 1];
            __half h0 = __float2half_rn(v0);
            __half h1 = __float2half_rn(v1);
            __half l0 = __float2half_rn(v0 - __half2float(h0));
            __half l1 = __float2half_rn(v1 - __half2float(h1));
            size_t ob = (size_t)(b * NTOK + ii) * CDIM + col;
            *reinterpret_cast<__half2*>(&g_Ahi[ob]) = __halves2half2(h0, h1);
            *reinterpret_cast<__half2*>(&g_Alo[ob]) = __halves2half2(l0, l1);
        }
    }
}

// ---------------------------------------------------------------------------
// Launch
// ---------------------------------------------------------------------------
extern "C" void kernel_launch(void* const* d_in, const int* in_sizes, int n_in,
                              void* d_out, int out_size)
{
    (void)in_sizes; (void)n_in; (void)out_size;
    const float* x     = (const float*)d_in[0];
    const float* mask  = (const float*)d_in[1];
    const float* wq    = (const float*)d_in[2];
    const float* bq    = (const float*)d_in[3];
    const float* wk    = (const float*)d_in[4];
    const float* wv    = (const float*)d_in[5];
    const float* bv    = (const float*)d_in[6];
    const float* cw1   = (const float*)d_in[7];
    const float* cb1   = (const float*)d_in[8];
    const float* cw2   = (const float*)d_in[9];
    const float* cb2   = (const float*)d_in[10];
    const float* tau   = (const float*)d_in[11];
    const float* wproj = (const float*)d_in[12];
    const float* bproj = (const float*)d_in[13];
    float* out = (float*)d_out;

    float *pBcat;
    __half *pQh, *pKh, *pVh, *pAhi, *pAlo, *pW;
    cudaGetSymbolAddress((void**)&pQh,   g_Qh);
    cudaGetSymbolAddress((void**)&pKh,   g_Kh);
    cudaGetSymbolAddress((void**)&pVh,   g_Vh);
    cudaGetSymbolAddress((void**)&pBcat, g_bcat);
    cudaGetSymbolAddress((void**)&pAhi,  g_Ahi);
    cudaGetSymbolAddress((void**)&pAlo,  g_Alo);
    cudaGetSymbolAddress((void**)&pW,    g_W);

    cudaFuncSetAttribute(gemm_wres_kernel, cudaFuncAttributeMaxDynamicSharedMemorySize,
                         GEMM_SMEM);

    const int xn4 = MROWS * CDIM / 4;
    const int PROJ_OFF = CDIM * 1152;

    convert_split_kernel<<<(xn4 + 255) / 256, 256>>>(x, pAhi, pAlo, xn4);
    w_fp16_kernel<<<144, 256>>>(wq, pW, 1152, 0);
    w_fp16_kernel<<<144, 256>>>(wk, pW, 1152, 384);
    w_fp16_kernel<<<144, 256>>>(wv, pW, 1152, 768);
    bias_cat_kernel<<<5, 256>>>(bq, bv);

    // QKV: grid (9, 64), each CTA does 9 row-blocks (rb = by + it*64)
    gemm_wres_kernel<<<dim3(9, 64), 256, GEMM_SMEM>>>(
        pAhi, pAlo, pW, pBcat, pQh, pKh, pVh, 1152, 1, 9);

    cpb_kernel<<<225, 128>>>(cw1, cb1, cw2, cb2, tau);
    attn_tc_kernel<<<dim3(NWIN, NHEADS), 128>>>(mask);

    w_fp16_kernel<<<144, 256>>>(wproj, pW + PROJ_OFF, 384, 0);
    // proj: grid (3, 192), each CTA does 3 row-blocks
    gemm_wres_kernel<<<dim3(3, 192), 256, GEMM_SMEM>>>(
        pAhi, pAlo, pW + PROJ_OFF, bproj, out, nullptr, nullptr, 384, 0, 3);
}